// round 8
// baseline (speedup 1.0000x reference)
#include <cuda_runtime.h>
#include <math.h>

#define T_LEN 32
#define KP    2048
#define CPB   14                       // columns per block (1 warp per column)
#define BLOCK (CPB * 32)               // 448 threads, 14 warps
#define GRID  147                      // ceil(2048/14) <= 148 SMs -> single wave, co-resident
#define FLAGW 160                      // padded flag row

// sp = sqrt(1/32); 0.5/sp^2 = 16 exactly
#define LOG_SP     (-1.7328679513998633f)
#define HALF_L2PI  (0.9189385332046727f)
#define LOG_K      (7.6246189861593985f)
#define C2EXP      (-23.083120654223414f)   // -16 * log2(e)
#define L2E        (1.4426950408889634f)
#define F_INF      (__int_as_float(0x7f800000))

__device__ float g_zs[T_LEN * KP];
__device__ float g_A [T_LEN * KP];
__device__ float g_rb[T_LEN][KP];
__device__ int   g_flag[T_LEN][FLAGW];   // per-CTA completion flags per step

// packed f32x2 ops (sm_103a)
#define F2ADD(o,a,b)   asm("add.rn.f32x2 %0,%1,%2;"    : "=l"(o) : "l"(a), "l"(b))
#define F2MUL(o,a,b)   asm("mul.rn.f32x2 %0,%1,%2;"    : "=l"(o) : "l"(a), "l"(b))
#define F2FMA(o,a,b,c) asm("fma.rn.f32x2 %0,%1,%2,%3;" : "=l"(o) : "l"(a), "l"(b), "l"(c))

__device__ __forceinline__ unsigned long long f2pk(float lo, float hi) {
    unsigned long long r; asm("mov.b64 %0,{%1,%2};" : "=l"(r) : "f"(lo), "f"(hi)); return r;
}
__device__ __forceinline__ void f2un(float& lo, float& hi, unsigned long long v) {
    asm("mov.b64 {%0,%1},%2;" : "=f"(lo), "=f"(hi) : "l"(v));
}
__device__ __forceinline__ float ex2(float t) {
    float r; asm("ex2.approx.ftz.f32 %0,%1;" : "=f"(r) : "f"(t)); return r;
}

__global__ void init_kernel() {
    int i = blockIdx.x * blockDim.x + threadIdx.x;
    for (int j = i; j < T_LEN * FLAGW; j += 512)
        ((int*)g_flag)[j] = 0;
}

// decentralized barrier: wait until all GRID flags for phase t are set
__device__ __forceinline__ void wait_flags(int t) {
    const int tid = threadIdx.x;
    if (tid < 32) {
        volatile int* f = &g_flag[t][0];
        bool ok;
        do {
            int v = 1;
            #pragma unroll
            for (int b = 0; b < 5; b++) {
                int idx = tid + b * 32;
                if (idx < GRID) v &= f[idx];
            }
            ok = __all_sync(0xffffffffu, v != 0);
        } while (!ok);
    }
    __syncthreads();
    __threadfence();
}

__device__ __forceinline__ void post_flag(int t) {
    __threadfence();
    __syncthreads();
    if (threadIdx.x == 0) __stcg(&g_flag[t][blockIdx.x], 1);
}

__global__ void __launch_bounds__(BLOCK) main_kernel(const float* __restrict__ means,
                                                     const float* __restrict__ log_stds,
                                                     const float* __restrict__ eps,
                                                     float* __restrict__ out) {
    __shared__ __align__(16) float lz[KP];    // -z_{t-1}
    __shared__ __align__(16) float lu[KP];    // (r_j - x) * log2(e)
    __shared__ float red[CPB + 2];

    const int tid  = threadIdx.x;
    const int wid  = tid >> 5;
    const int lane = tid & 31;
    const int k    = blockIdx.x * CPB + wid;   // this warp's column

    // ---- fused setup: zs, A, r0 (one element per thread; grid covers 65536) ----
    {
        int idx = blockIdx.x * BLOCK + tid;
        if (idx < T_LEN * KP) {
            int t = idx >> 11;
            int kk = idx & (KP - 1);
            float mu = means[t];
            float sg = expf(log_stds[t]);
            float z  = fmaf(sg, eps[idx], mu);
            float zq = (z - mu) / sg;
            float lq = fmaf(-0.5f * zq, zq, -logf(sg)) - HALF_L2PI;
            g_zs[idx] = z;
            g_A[idx]  = -LOG_SP - HALF_L2PI - lq;
            if (t == 0) {
                float zz = z * 5.656854249492380f;   // z / sp
                __stcg(&g_rb[0][kk], fmaf(-0.5f * zz, zz, -LOG_SP) - HALF_L2PI - lq);
            }
        }
        post_flag(0);
    }

    // ---- 31 fused scan steps ----
    for (int t = 1; t < T_LEN; t++) {
        wait_flags(t - 1);

        // prologue pass 1: load r + z, local max of r
        const float* __restrict__ zrow = g_zs + (t - 1) * KP;
        float lmax = -F_INF;
        for (int j = tid; j < KP; j += BLOCK) {
            float rv = __ldcg(&g_rb[t - 1][j]);
            lu[j] = rv;
            lz[j] = -zrow[j];
            lmax = fmaxf(lmax, rv);
        }
        #pragma unroll
        for (int m = 16; m; m >>= 1)
            lmax = fmaxf(lmax, __shfl_xor_sync(0xffffffffu, lmax, m));
        if (lane == 0) red[wid] = lmax;
        __syncthreads();
        float x = red[0];
        #pragma unroll
        for (int w = 1; w < CPB; w++) x = fmaxf(x, red[w]);
        // prologue pass 2: lu = (r - x) * log2e
        for (int j = tid; j < KP; j += BLOCK)
            lu[j] = (lu[j] - x) * L2E;
        __syncthreads();

        if (k < KP) {
            const float zk = g_zs[t * KP + k];
            const float ak = g_A [t * KP + k];
            const unsigned long long zk2 = f2pk(zk, zk);
            const unsigned long long c2v = f2pk(C2EXP, C2EXP);

            float S0 = 0.0f, S1 = 0.0f;
            #pragma unroll 8
            for (int i = 0; i < KP / 64; i++) {
                int jj = i * 32 + lane;                  // float2 index
                unsigned long long zu = *reinterpret_cast<const unsigned long long*>(lz + 2 * jj);
                unsigned long long uu = *reinterpret_cast<const unsigned long long*>(lu + 2 * jj);
                unsigned long long d, dd, tt;
                F2ADD(d, zk2, zu);                       // d = zk - z'
                F2MUL(dd, d, d);
                F2FMA(tt, dd, c2v, uu);                  // t = C2*d^2 + (r-x)*log2e  (<= 0)
                float t0, t1;
                f2un(t0, t1, tt);
                S0 += ex2(t0);                           // MUFU: flushes huge-negative to 0
                S1 += ex2(t1);
            }
            float S = S0 + S1;
            #pragma unroll
            for (int m = 16; m; m >>= 1)
                S += __shfl_xor_sync(0xffffffffu, S, m);
            if (lane == 0)
                __stcg(&g_rb[t][k], x + ak + logf(fmaxf(S, 1e-37f)) - LOG_K);
        }
        post_flag(t);
    }

    // ---- final factor: only CTA 0 ----
    if (blockIdx.x != 0) return;
    wait_flags(T_LEN - 1);

    const float* __restrict__ zrow = g_zs + (T_LEN - 1) * KP;
    float lr = -F_INF, lL = -F_INF;
    for (int j = tid; j < KP; j += BLOCK) {
        float rv = __ldcg(&g_rb[T_LEN - 1][j]);
        float z  = zrow[j];
        float dd = 0.5f - z;
        float Lv = fmaf(-0.5f * dd, dd, -HALF_L2PI);
        lu[j] = rv;
        lz[j] = Lv;
        lr = fmaxf(lr, rv);
        lL = fmaxf(lL, Lv);
    }
    #pragma unroll
    for (int m = 16; m; m >>= 1) {
        lr = fmaxf(lr, __shfl_xor_sync(0xffffffffu, lr, m));
        lL = fmaxf(lL, __shfl_xor_sync(0xffffffffu, lL, m));
    }
    if (lane == 0) { red[wid] = lr; }
    __syncthreads();
    float x = red[0];
    #pragma unroll
    for (int w = 1; w < CPB; w++) x = fmaxf(x, red[w]);
    __syncthreads();
    if (lane == 0) { red[wid] = lL; }
    __syncthreads();
    float y = red[0];
    #pragma unroll
    for (int w = 1; w < CPB; w++) y = fmaxf(y, red[w]);

    float S = 0.0f;
    for (int j = tid; j < KP; j += BLOCK)
        S += ex2(((lu[j] - x) + (lz[j] - y)) * L2E);
    #pragma unroll
    for (int m = 16; m; m >>= 1)
        S += __shfl_xor_sync(0xffffffffu, S, m);
    if (lane == 0) red[wid] = S;
    __syncthreads();
    if (tid == 0) {
        float tot = 0.0f;
        #pragma unroll
        for (int w = 0; w < CPB; w++) tot += red[w];
        out[0] = x + y + logf(tot) - LOG_K;
    }
}

extern "C" void kernel_launch(void* const* d_in, const int* in_sizes, int n_in,
                              void* d_out, int out_size) {
    const float* means    = (const float*)d_in[0];
    const float* log_stds = (const float*)d_in[1];
    const float* eps      = (const float*)d_in[2];
    float* out = (float*)d_out;

    init_kernel<<<1, 512>>>();
    main_kernel<<<GRID, BLOCK>>>(means, log_stds, eps, out);
}

// round 9
// speedup vs baseline: 3.3057x; 3.3057x over previous
#include <cuda_runtime.h>
#include <math.h>

#define T_LEN 32
#define KP    2048
#define CPB   16                       // columns per block
#define GPC   16                       // threads per column (2 columns share a warp)
#define BLOCK 256
#define GRID  128                      // 128*16 = 2048 columns, single wave

// sp = sqrt(1/32); 0.5/sp^2 = 16 exactly
#define LOG_SP     (-1.7328679513998633f)
#define HALF_L2PI  (0.9189385332046727f)
#define LOG_K      (7.6246189861593985f)
#define C2EXP      (-23.083120654223414f)   // -16 * log2(e)
#define L2E        (1.4426950408889634f)
#define F_INF      (__int_as_float(0x7f800000))

__device__ float g_zs[T_LEN * KP];
__device__ float g_A [T_LEN * KP];
__device__ float g_rb[T_LEN][KP];

// packed f32x2 ops (sm_103a)
#define F2ADD(o,a,b)   asm("add.rn.f32x2 %0,%1,%2;"    : "=l"(o) : "l"(a), "l"(b))
#define F2MUL(o,a,b)   asm("mul.rn.f32x2 %0,%1,%2;"    : "=l"(o) : "l"(a), "l"(b))
#define F2FMA(o,a,b,c) asm("fma.rn.f32x2 %0,%1,%2,%3;" : "=l"(o) : "l"(a), "l"(b), "l"(c))

__device__ __forceinline__ unsigned long long f2pk(float lo, float hi) {
    unsigned long long r; asm("mov.b64 %0,{%1,%2};" : "=l"(r) : "f"(lo), "f"(hi)); return r;
}
__device__ __forceinline__ void f2un(float& lo, float& hi, unsigned long long v) {
    asm("mov.b64 {%0,%1},%2;" : "=f"(lo), "=f"(hi) : "l"(v));
}
__device__ __forceinline__ float ex2(float t) {
    float r; asm("ex2.approx.ftz.f32 %0,%1;" : "=f"(r) : "f"(t)); return r;
}

// Setup: zs = mu + sigma*eps; A = -log(sp)-0.5log2pi-log_q; r0
__global__ void __launch_bounds__(256) setup_kernel(const float* __restrict__ means,
                                                    const float* __restrict__ log_stds,
                                                    const float* __restrict__ eps) {
    int idx = blockIdx.x * 256 + threadIdx.x;      // grid covers T_LEN*KP exactly
    int t = idx >> 11;
    int k = idx & (KP - 1);
    float mu = means[t];
    float sg = expf(log_stds[t]);
    float z  = fmaf(sg, eps[idx], mu);
    float zq = (z - mu) / sg;
    float lq = fmaf(-0.5f * zq, zq, -logf(sg)) - HALF_L2PI;
    g_zs[idx] = z;
    g_A[idx]  = -LOG_SP - HALF_L2PI - lq;
    if (t == 0) {
        float zz = z * 5.656854249492380f;         // z / sp
        g_rb[0][k] = fmaf(-0.5f * zz, zz, -LOG_SP) - HALF_L2PI - lq;
    }
}

// One scan step with PDL: prologue (z row) overlaps predecessor; sync only before r.
__global__ void __launch_bounds__(BLOCK) step_kernel(int t) {
    __shared__ __align__(16) float lz[KP];    // -z_{t-1}
    __shared__ __align__(16) float lu[KP];    // (r_j - x) * log2(e)
    __shared__ float red[BLOCK / 32];

    const int tid  = threadIdx.x;
    const int wid  = tid >> 5;
    const int lane = tid & 31;
    const int c    = tid >> 4;                 // column-in-block 0..15
    const int g    = tid & (GPC - 1);
    const int k    = blockIdx.x * CPB + c;

    cudaTriggerProgrammaticLaunchCompletion();         // let successor launch now
    if (t == 1) cudaGridDependencySynchronize();       // setup may still be running

    // ---- independent prologue (safe pre-sync for t>=2: setup data only) ----
    const float* __restrict__ zrow = g_zs + (t - 1) * KP;
    #pragma unroll
    for (int i = 0; i < KP / BLOCK; i++)
        lz[tid + i * BLOCK] = -zrow[tid + i * BLOCK];
    const float zk = g_zs[t * KP + k];
    const float ak = g_A [t * KP + k];

    cudaGridDependencySynchronize();                   // wait for r_{t-1}

    // ---- load r, global max (local to block), build lu ----
    const float* __restrict__ rin = g_rb[t - 1];
    float rv[KP / BLOCK];
    float lm = -F_INF;
    #pragma unroll
    for (int i = 0; i < KP / BLOCK; i++) {
        rv[i] = rin[tid + i * BLOCK];
        lm = fmaxf(lm, rv[i]);
    }
    #pragma unroll
    for (int m = 16; m; m >>= 1)
        lm = fmaxf(lm, __shfl_xor_sync(0xffffffffu, lm, m));
    if (lane == 0) red[wid] = lm;
    __syncthreads();
    float x = red[0];
    #pragma unroll
    for (int w = 1; w < BLOCK / 32; w++) x = fmaxf(x, red[w]);
    #pragma unroll
    for (int i = 0; i < KP / BLOCK; i++)
        lu[tid + i * BLOCK] = (rv[i] - x) * L2E;
    __syncthreads();

    // ---- mainloop: S = sum_j 2^(C2*d^2 + (r_j-x)*log2e) ----
    const unsigned long long zk2 = f2pk(zk, zk);
    const unsigned long long c2v = f2pk(C2EXP, C2EXP);
    float S0 = 0.0f, S1 = 0.0f;
    #pragma unroll 8
    for (int i = 0; i < KP / (2 * GPC); i++) {         // 64 iters, 2 pairs each
        int jj = i * GPC + g;                          // float2 index; half-warps mirror -> LDS broadcast
        unsigned long long zu = *reinterpret_cast<const unsigned long long*>(lz + 2 * jj);
        unsigned long long uu = *reinterpret_cast<const unsigned long long*>(lu + 2 * jj);
        unsigned long long d, dd, tt;
        F2ADD(d, zk2, zu);                             // d = zk - z'
        F2MUL(dd, d, d);
        F2FMA(tt, dd, c2v, uu);                        // exponent (<= 0)
        float t0, t1;
        f2un(t0, t1, tt);
        S0 += ex2(t0);                                 // MUFU, flushes to 0 when tiny
        S1 += ex2(t1);
    }
    float S = S0 + S1;
    #pragma unroll
    for (int m = GPC / 2; m; m >>= 1)
        S += __shfl_xor_sync(0xffffffffu, S, m, GPC);
    if (g == 0)
        g_rb[t][k] = x + ak + logf(fmaxf(S, 1e-37f)) - LOG_K;
}

// Final: out = x + y + log(sum_j exp(r_j - x)*exp(L_j - y)) - logK
__global__ void __launch_bounds__(BLOCK) final_kernel(float* __restrict__ out) {
    __shared__ float sr[KP];
    __shared__ float sL[KP];
    __shared__ float red[2 * (BLOCK / 32)];
    const int tid  = threadIdx.x;
    const int wid  = tid >> 5;
    const int lane = tid & 31;

    cudaGridDependencySynchronize();

    const float* __restrict__ zrow = g_zs + (T_LEN - 1) * KP;
    const float* __restrict__ rin  = g_rb[T_LEN - 1];
    float lr = -F_INF, lL = -F_INF;
    #pragma unroll
    for (int i = 0; i < KP / BLOCK; i++) {
        int j = tid + i * BLOCK;
        float r  = rin[j];
        float dd = 0.5f - zrow[j];
        float Lv = fmaf(-0.5f * dd, dd, -HALF_L2PI);
        sr[j] = r; sL[j] = Lv;
        lr = fmaxf(lr, r);
        lL = fmaxf(lL, Lv);
    }
    #pragma unroll
    for (int m = 16; m; m >>= 1) {
        lr = fmaxf(lr, __shfl_xor_sync(0xffffffffu, lr, m));
        lL = fmaxf(lL, __shfl_xor_sync(0xffffffffu, lL, m));
    }
    if (lane == 0) { red[wid] = lr; red[BLOCK / 32 + wid] = lL; }
    __syncthreads();
    float x = red[0], y = red[BLOCK / 32];
    #pragma unroll
    for (int w = 1; w < BLOCK / 32; w++) {
        x = fmaxf(x, red[w]);
        y = fmaxf(y, red[BLOCK / 32 + w]);
    }

    float S = 0.0f;
    #pragma unroll
    for (int i = 0; i < KP / BLOCK; i++) {
        int j = tid + i * BLOCK;
        S += ex2(((sr[j] - x) + (sL[j] - y)) * L2E);
    }
    #pragma unroll
    for (int m = 16; m; m >>= 1)
        S += __shfl_xor_sync(0xffffffffu, S, m);
    if (lane == 0) red[wid] = S;
    __syncthreads();
    if (tid == 0) {
        float tot = 0.0f;
        #pragma unroll
        for (int w = 0; w < BLOCK / 32; w++) tot += red[w];
        out[0] = x + y + logf(tot) - LOG_K;
    }
}

extern "C" void kernel_launch(void* const* d_in, const int* in_sizes, int n_in,
                              void* d_out, int out_size) {
    const float* means    = (const float*)d_in[0];
    const float* log_stds = (const float*)d_in[1];
    const float* eps      = (const float*)d_in[2];
    float* out = (float*)d_out;

    setup_kernel<<<(T_LEN * KP) / 256, 256>>>(means, log_stds, eps);

    cudaLaunchAttribute attr[1];
    attr[0].id = cudaLaunchAttributeProgrammaticStreamSerialization;
    attr[0].val.programmaticStreamSerializationAllowed = 1;

    cudaLaunchConfig_t cfg = {};
    cfg.gridDim  = dim3(GRID, 1, 1);
    cfg.blockDim = dim3(BLOCK, 1, 1);
    cfg.dynamicSmemBytes = 0;
    cfg.stream = 0;
    cfg.attrs = attr;
    cfg.numAttrs = 1;

    for (int t = 1; t < T_LEN; t++)
        cudaLaunchKernelEx(&cfg, step_kernel, t);

    cudaLaunchConfig_t cfgf = cfg;
    cfgf.gridDim = dim3(1, 1, 1);
    cudaLaunchKernelEx(&cfgf, final_kernel, out);
}